// round 17
// baseline (speedup 1.0000x reference)
#include <cuda_runtime.h>
#include <cuda_fp16.h>
#include <cstdint>
#include <math.h>

constexpr int Bv = 4, Sv = 2048, Ev = 1024, Hv = 16;
constexpr int BSz = Bv * Sv;   // 8192

// Scratch (__device__ globals; no allocation)
__device__ __half g_Xh[BSz * Ev];         // fp16 x
__device__ __half g_Qh[BSz * Ev];         // fp16 Q, pre-scaled by 1/32
__device__ __half g_Kh[BSz * Ev];
__device__ __half g_Vh[BSz * Ev];
__device__ __half g_Ch[BSz * Ev];         // fp16 attention context
__device__ float  g_O[BSz * Ev];          // main_out + x (fp32, for LN)
__device__ __half g_WT[4ull * Ev * Ev];   // fp16 transposed weights [n][k]

// ---------------------------------------------------------------------------
// helpers
// ---------------------------------------------------------------------------
__device__ __forceinline__ uint32_t smem_u32(const void* p) {
    uint32_t a;
    asm("{ .reg .u64 t; cvta.to.shared.u64 t, %1; cvt.u32.u64 %0, t; }" : "=r"(a) : "l"(p));
    return a;
}
__device__ __forceinline__ void mma16(float* d, const uint32_t* a, uint32_t b0, uint32_t b1) {
    asm volatile(
        "mma.sync.aligned.m16n8k16.row.col.f32.f16.f16.f32 "
        "{%0,%1,%2,%3}, {%4,%5,%6,%7}, {%8,%9}, {%0,%1,%2,%3};"
        : "+f"(d[0]), "+f"(d[1]), "+f"(d[2]), "+f"(d[3])
        : "r"(a[0]), "r"(a[1]), "r"(a[2]), "r"(a[3]), "r"(b0), "r"(b1));
}
__device__ __forceinline__ void ldsm4(uint32_t* r, uint32_t addr) {
    asm volatile("ldmatrix.sync.aligned.m8n8.x4.shared.b16 {%0,%1,%2,%3}, [%4];"
                 : "=r"(r[0]), "=r"(r[1]), "=r"(r[2]), "=r"(r[3]) : "r"(addr));
}
__device__ __forceinline__ void ldsm4t(uint32_t* r, uint32_t addr) {
    asm volatile("ldmatrix.sync.aligned.m8n8.x4.trans.shared.b16 {%0,%1,%2,%3}, [%4];"
                 : "=r"(r[0]), "=r"(r[1]), "=r"(r[2]), "=r"(r[3]) : "r"(addr));
}
__device__ __forceinline__ void cpa16(uint32_t dst, const void* src) {
    asm volatile("cp.async.cg.shared.global [%0], [%1], 16;" :: "r"(dst), "l"(src));
}
#define CP_COMMIT() asm volatile("cp.async.commit_group;" ::: "memory")
#define CP_WAIT(n)  asm volatile("cp.async.wait_group %0;" :: "n"(n) : "memory")
__device__ __forceinline__ uint32_t h2u(__half2 h) { return *(uint32_t*)&h; }

// ---------------------------------------------------------------------------
// prep: fp32 -> fp16 convert / fused transpose-convert of 4 weight matrices
// ---------------------------------------------------------------------------
__global__ void cvtX(const float* __restrict__ in, __half* __restrict__ out) {
    size_t i = ((size_t)blockIdx.x * 256 + threadIdx.x) * 4;
    float4 v = *(const float4*)(in + i);
    __half2* o = (__half2*)(out + i);
    o[0] = __floats2half2_rn(v.x, v.y);
    o[1] = __floats2half2_rn(v.z, v.w);
}
__global__ void cvtW4(const float* __restrict__ W0, const float* __restrict__ W1,
                      const float* __restrict__ W2, const float* __restrict__ W3,
                      __half* __restrict__ out) {
    __shared__ float t[32][33];
    const float* in = (blockIdx.z == 0) ? W0 : (blockIdx.z == 1) ? W1
                    : (blockIdx.z == 2) ? W2 : W3;
    __half* op = out + (size_t)blockIdx.z * Ev * Ev;
    int k0 = blockIdx.y * 32, n0 = blockIdx.x * 32;
    for (int i = threadIdx.y; i < 32; i += 8)
        t[i][threadIdx.x] = in[(size_t)(k0 + i) * 1024 + n0 + threadIdx.x];
    __syncthreads();
    for (int i = threadIdx.y; i < 32; i += 8)
        op[(size_t)(n0 + i) * 1024 + k0 + threadIdx.x] = __float2half(t[threadIdx.x][i]);
}

// ---------------------------------------------------------------------------
// fp16 GEMM: C = A @ WT^T + bias (*scale); HOUT=false adds fp32 residual X.
// 256 thr, 8 warps (2M x 4N), warp tile 64x32, CTA tile 128x128, K-chunk 64,
// 3-stage cp.async smem pipeline + 2-deep register fragment pipeline:
// fragments for k-step kk+1 load while kk's 16 MMAs issue.
// ---------------------------------------------------------------------------
constexpr int GPH = 72;
constexpr int GSTB = 2 * 128 * GPH * 2;   // stage bytes = 36864
constexpr int GEMM_SMEM = 3 * GSTB;       // 110592

template <bool HOUT>
__global__ __launch_bounds__(256, 2) void gemm_h(const __half* __restrict__ A,
                                                 const __half* __restrict__ WT,
                                                 const float* __restrict__ bias,
                                                 void* __restrict__ Cout, float scale,
                                                 const float* __restrict__ Xres) {
    extern __shared__ char sm[];
    const int tid = threadIdx.x, wid = tid >> 5, lane = tid & 31;
    const int gid = lane >> 2, tig = lane & 3;
    const int wm = wid >> 2, wn = wid & 3;        // 2 x 4 warp grid
    const int m0 = blockIdx.y * 128, n0 = blockIdx.x * 128;
    const uint32_t smb = smem_u32(sm);
    const int rsA = lane & 15, csA = (lane >> 4) * 8;
    const int rsB = (lane & 7) + ((lane >> 4) & 1) * 8, csB = ((lane >> 3) & 1) * 8;

    auto issue = [&](int c) {
        uint32_t dA = smb + (uint32_t)((c % 3) * GSTB);
        uint32_t dB = dA + 128 * GPH * 2;
        const __half* pa = A  + (size_t)m0 * 1024 + c * 64;
        const __half* pb = WT + (size_t)n0 * 1024 + c * 64;
        #pragma unroll
        for (int i = 0; i < 4; i++) {
            int unit = tid + i * 256, r = unit >> 3, u = unit & 7;
            cpa16(dA + (uint32_t)(r * GPH + u * 8) * 2, pa + (size_t)r * 1024 + u * 8);
            cpa16(dB + (uint32_t)(r * GPH + u * 8) * 2, pb + (size_t)r * 1024 + u * 8);
        }
    };

    float acc[4][4][4] = {};
    issue(0); CP_COMMIT();
    issue(1); CP_COMMIT();

    uint32_t a[2][4][4], bb[2][2][4];

    for (int c = 0; c < 16; c++) {
        CP_WAIT(1);
        __syncthreads();
        if (c + 2 < 16) issue(c + 2);
        CP_COMMIT();   // always commit (possibly empty) so CP_WAIT(1) pins group c+1
        uint32_t bA = smb + (uint32_t)((c % 3) * GSTB);
        uint32_t aB0 = bA + (uint32_t)((wm * 64 + rsA) * GPH + csA) * 2;
        uint32_t bB0 = bA + 128 * GPH * 2 + (uint32_t)((wn * 32 + rsB) * GPH + csB) * 2;

        // prologue: fragments for kk=0
        #pragma unroll
        for (int mt = 0; mt < 4; mt++)
            ldsm4(a[0][mt], aB0 + (uint32_t)(mt * 16 * GPH) * 2);
        ldsm4(bb[0][0], bB0);
        ldsm4(bb[0][1], bB0 + 16 * GPH * 2);

        #pragma unroll
        for (int kk = 0; kk < 4; kk++) {
            const int cur = kk & 1, nxt = cur ^ 1;
            if (kk < 3) {   // prefetch kk+1 fragments while kk's MMAs issue
                #pragma unroll
                for (int mt = 0; mt < 4; mt++)
                    ldsm4(a[nxt][mt], aB0 + (uint32_t)(mt * 16 * GPH) * 2 + (kk + 1) * 32);
                ldsm4(bb[nxt][0], bB0 + (kk + 1) * 32);
                ldsm4(bb[nxt][1], bB0 + 16 * GPH * 2 + (kk + 1) * 32);
            }
            #pragma unroll
            for (int mt = 0; mt < 4; mt++)
                #pragma unroll
                for (int nt = 0; nt < 4; nt++)
                    mma16(acc[mt][nt], a[cur][mt], bb[cur][nt >> 1][(nt & 1) * 2],
                          bb[cur][nt >> 1][(nt & 1) * 2 + 1]);
        }
        // no bottom sync: next iteration's top sync orders stage reuse (3 stages)
    }

    #pragma unroll
    for (int mt = 0; mt < 4; mt++) {
        int row = m0 + wm * 64 + mt * 16 + gid;
        #pragma unroll
        for (int nt = 0; nt < 4; nt++) {
            int col = n0 + wn * 32 + nt * 8 + tig * 2;
            float b0 = bias[col], b1 = bias[col + 1];
            float v0 = (acc[mt][nt][0] + b0) * scale, v1 = (acc[mt][nt][1] + b1) * scale;
            float v2 = (acc[mt][nt][2] + b0) * scale, v3 = (acc[mt][nt][3] + b1) * scale;
            if (HOUT) {
                __half* C = (__half*)Cout;
                *(__half2*)(C + (size_t)row * 1024 + col) = __floats2half2_rn(v0, v1);
                *(__half2*)(C + (size_t)(row + 8) * 1024 + col) = __floats2half2_rn(v2, v3);
            } else {
                float* C = (float*)Cout;
                float2 x0 = *(const float2*)(Xres + (size_t)row * 1024 + col);
                float2 x1 = *(const float2*)(Xres + (size_t)(row + 8) * 1024 + col);
                *(float2*)(C + (size_t)row * 1024 + col) = make_float2(v0 + x0.x, v1 + x0.y);
                *(float2*)(C + (size_t)(row + 8) * 1024 + col) = make_float2(v2 + x1.x, v3 + x1.y);
            }
        }
    }
}

// ---------------------------------------------------------------------------
// fp16 flash attention, split-softmax across key-halves (unchanged from R12).
// ---------------------------------------------------------------------------
constexpr int OQ = 0, OK = 18432, OV = 36864, OVB = 18432;
constexpr int OM = 73728, ORM = 74240, ORS = 75264;
constexpr int ATTN_SMEM = 76288;

__global__ __launch_bounds__(512) void attn_h(const __half* __restrict__ Q,
                                              const __half* __restrict__ Kg,
                                              const __half* __restrict__ Vg,
                                              const float* __restrict__ mask,
                                              __half* __restrict__ C) {
    extern __shared__ char sm[];
    const int tid = threadIdx.x, wid = tid >> 5, lane = tid & 31;
    const int gid = lane >> 2, tig = lane & 3;
    const int wm = wid >> 1, wn = wid & 1;       // 8 x 2 warp grid
    const int b = blockIdx.y >> 4, h = blockIdx.y & 15;
    const int q0 = blockIdx.x * 128;
    const uint32_t smb = smem_u32(sm);
    const int rsA = lane & 15, csA = (lane >> 4) * 8;
    const int rsB = (lane & 7) + ((lane >> 4) & 1) * 8;
    const int csB = ((lane >> 3) & 1) * 8;

    const __half* Qg  = Q  + ((size_t)(b * Sv + q0)) * Ev + h * 64;
    const __half* Kgp = Kg + ((size_t)b * Sv) * Ev + h * 64;
    const __half* Vgp = Vg + ((size_t)b * Sv) * Ev + h * 64;

    auto issueK = [&](int t) {
        const __half* p = Kgp + (size_t)(t * 128) * Ev;
        #pragma unroll
        for (int i = 0; i < 2; i++) {
            int unit = tid + i * 512, r = unit >> 3, u = unit & 7;
            cpa16(smb + OK + (uint32_t)(r * GPH + u * 8) * 2, p + (size_t)r * Ev + u * 8);
        }
    };
    auto issueV = [&](int t) {
        const __half* p = Vgp + (size_t)(t * 128) * Ev;
        uint32_t dst = smb + OV + (t & 1) * OVB;
        #pragma unroll
        for (int i = 0; i < 2; i++) {
            int unit = tid + i * 512, r = unit >> 3, u = unit & 7;
            cpa16(dst + (uint32_t)(r * GPH + u * 8) * 2, p + (size_t)r * Ev + u * 8);
        }
    };
    auto issueM = [&](int t) {
        if (tid < 32)
            cpa16(smb + OM + tid * 16, mask + (size_t)b * Sv + t * 128 + tid * 4);
    };

    #pragma unroll
    for (int i = 0; i < 2; i++) {
        int unit = tid + i * 512, r = unit >> 3, u = unit & 7;
        cpa16(smb + OQ + (uint32_t)(r * GPH + u * 8) * 2, Qg + (size_t)r * Ev + u * 8);
    }
    issueK(0); issueV(0); issueM(0);
    CP_COMMIT();

    float o[8][4] = {};
    float m_run0 = -INFINITY, m_run1 = -INFINITY, l_run0 = 0.f, l_run1 = 0.f;
    float* sMask = (float*)(sm + OM);
    const int row0 = wm * 16 + gid, row1 = row0 + 8;

    for (int t = 0; t < 16; t++) {
        CP_WAIT(0);
        __syncthreads();

        float s[8][4] = {};
        {
            uint32_t aQ = smb + OQ + (uint32_t)((wm * 16 + rsA) * GPH + csA) * 2;
            uint32_t kB = smb + OK + (uint32_t)((wn * 64 + rsB) * GPH + csB) * 2;
            #pragma unroll
            for (int kk = 0; kk < 4; kk++) {
                uint32_t a[4];
                ldsm4(a, aQ + kk * 32);
                #pragma unroll
                for (int kg = 0; kg < 4; kg++) {
                    uint32_t bbv[4];
                    ldsm4(bbv, kB + kg * 16 * GPH * 2 + kk * 32);
                    mma16(s[kg * 2], a, bbv[0], bbv[1]);
                    mma16(s[kg * 2 + 1], a, bbv[2], bbv[3]);
                }
            }
        }

        float pm0 = -INFINITY, pm1 = -INFINITY;
        #pragma unroll
        for (int ng = 0; ng < 8; ng++) {
            int col = wn * 64 + ng * 8 + tig * 2;
            float mv0 = sMask[col] * (-1e9f), mv1 = sMask[col + 1] * (-1e9f);
            s[ng][0] += mv0; s[ng][1] += mv1;
            s[ng][2] += mv0; s[ng][3] += mv1;
            pm0 = fmaxf(pm0, fmaxf(s[ng][0], s[ng][1]));
            pm1 = fmaxf(pm1, fmaxf(s[ng][2], s[ng][3]));
        }
        __syncthreads();
        if (t + 1 < 16) { issueK(t + 1); issueV(t + 1); issueM(t + 1); CP_COMMIT(); }

        pm0 = fmaxf(pm0, __shfl_xor_sync(0xffffffffu, pm0, 1));
        pm0 = fmaxf(pm0, __shfl_xor_sync(0xffffffffu, pm0, 2));
        pm1 = fmaxf(pm1, __shfl_xor_sync(0xffffffffu, pm1, 1));
        pm1 = fmaxf(pm1, __shfl_xor_sync(0xffffffffu, pm1, 2));
        float m_new0 = fmaxf(m_run0, pm0);
        float m_new1 = fmaxf(m_run1, pm1);
        float alpha0 = __expf(m_run0 - m_new0);
        float alpha1 = __expf(m_run1 - m_new1);
        float ps0 = 0.f, ps1 = 0.f;
        #pragma unroll
        for (int ng = 0; ng < 8; ng++) {
            s[ng][0] = __expf(s[ng][0] - m_new0);
            s[ng][1] = __expf(s[ng][1] - m_new0);
            s[ng][2] = __expf(s[ng][2] - m_new1);
            s[ng][3] = __expf(s[ng][3] - m_new1);
            ps0 += s[ng][0] + s[ng][1];
            ps1 += s[ng][2] + s[ng][3];
        }
        ps0 += __shfl_xor_sync(0xffffffffu, ps0, 1);
        ps0 += __shfl_xor_sync(0xffffffffu, ps0, 2);
        ps1 += __shfl_xor_sync(0xffffffffu, ps1, 1);
        ps1 += __shfl_xor_sync(0xffffffffu, ps1, 2);
        l_run0 = l_run0 * alpha0 + ps0;
        l_run1 = l_run1 * alpha1 + ps1;
        m_run0 = m_new0; m_run1 = m_new1;

        uint32_t pf[4][4];
        #pragma unroll
        for (int kc = 0; kc < 4; kc++) {
            pf[kc][0] = h2u(__floats2half2_rn(s[kc * 2][0], s[kc * 2][1]));
            pf[kc][1] = h2u(__floats2half2_rn(s[kc * 2][2], s[kc * 2][3]));
            pf[kc][2] = h2u(__floats2half2_rn(s[kc * 2 + 1][0], s[kc * 2 + 1][1]));
            pf[kc][3] = h2u(__floats2half2_rn(s[kc * 2 + 1][2], s[kc * 2 + 1][3]));
        }

        #pragma unroll
        for (int ng = 0; ng < 8; ng++) {
            o[ng][0] *= alpha0; o[ng][1] *= alpha0;
            o[ng][2] *= alpha1; o[ng][3] *= alpha1;
        }
        {
            uint32_t vB = smb + OV + (t & 1) * OVB + (uint32_t)((wn * 64 + rsA) * GPH + csA) * 2;
            #pragma unroll
            for (int kc = 0; kc < 4; kc++) {
                #pragma unroll
                for (int dg = 0; dg < 4; dg++) {
                    uint32_t bbv[4];
                    ldsm4t(bbv, vB + (uint32_t)(kc * 16 * GPH + dg * 16) * 2);
                    mma16(o[dg * 2], pf[kc], bbv[0], bbv[1]);
                    mma16(o[dg * 2 + 1], pf[kc], bbv[2], bbv[3]);
                }
            }
        }
    }

    float* sM = (float*)(sm + ORM);
    float* sL = (float*)(sm + ORS);
    if (tig == 0) {
        sM[row0 * 2 + wn] = m_run0;  sM[row1 * 2 + wn] = m_run1;
        sL[row0 * 2 + wn] = l_run0;  sL[row1 * 2 + wn] = l_run1;
    }
    __syncthreads();
    float mo0 = sM[row0 * 2 + (wn ^ 1)], mo1 = sM[row1 * 2 + (wn ^ 1)];
    float lo0 = sL[row0 * 2 + (wn ^ 1)], lo1 = sL[row1 * 2 + (wn ^ 1)];
    float mg0 = fmaxf(m_run0, mo0), mg1 = fmaxf(m_run1, mo1);
    float be0 = __expf(m_run0 - mg0), be1 = __expf(m_run1 - mg1);
    float beo0 = __expf(mo0 - mg0),  beo1 = __expf(mo1 - mg1);
    float lg0 = l_run0 * be0 + lo0 * beo0;
    float lg1 = l_run1 * be1 + lo1 * beo1;

    float* sO = (float*)sm;
    if (wn == 1) {
        #pragma unroll
        for (int ng = 0; ng < 8; ng++) {
            *(float2*)&sO[row0 * 68 + ng * 8 + tig * 2] =
                make_float2(o[ng][0] * be0, o[ng][1] * be0);
            *(float2*)&sO[row1 * 68 + ng * 8 + tig * 2] =
                make_float2(o[ng][2] * be1, o[ng][3] * be1);
        }
    }
    __syncthreads();
    if (wn == 0) {
        float inv0 = 1.f / lg0, inv1 = 1.f / lg1;
        #pragma unroll
        for (int ng = 0; ng < 8; ng++) {
            int col = ng * 8 + tig * 2;
            float2 p0 = *(float2*)&sO[row0 * 68 + col];
            float2 p1 = *(float2*)&sO[row1 * 68 + col];
            __half* C0 = C + ((size_t)(b * Sv + q0 + row0)) * Ev + h * 64 + col;
            __half* C1 = C + ((size_t)(b * Sv + q0 + row1)) * Ev + h * 64 + col;
            *(__half2*)C0 = __floats2half2_rn((o[ng][0] * be0 + p0.x) * inv0,
                                              (o[ng][1] * be0 + p0.y) * inv0);
            *(__half2*)C1 = __floats2half2_rn((o[ng][2] * be1 + p1.x) * inv1,
                                              (o[ng][3] * be1 + p1.y) * inv1);
        }
    }
}

// ---------------------------------------------------------------------------
// LayerNorm(pre-added main_out + x), float4 vectorized
// ---------------------------------------------------------------------------
__global__ __launch_bounds__(256) void ln_kernel(const float* __restrict__ MO,
                                                 const float* __restrict__ gamma,
                                                 const float* __restrict__ beta,
                                                 float* __restrict__ out) {
    const int r = blockIdx.x;
    const float* mo = MO + (size_t)r * Ev;

    float4 v = *(const float4*)(mo + threadIdx.x * 4);
    float s1 = v.x + v.y + v.z + v.w;
    float s2 = v.x * v.x + v.y * v.y + v.z * v.z + v.w * v.w;
    #pragma unroll
    for (int o = 16; o > 0; o >>= 1) {
        s1 += __shfl_xor_sync(0xffffffffu, s1, o);
        s2 += __shfl_xor_sync(0xffffffffu, s2, o);
    }
    __shared__ float sh1[8], sh2[8], stats[2];
    const int w = threadIdx.x >> 5, lane = threadIdx.x & 31;
    if (lane == 0) { sh1[w] = s1; sh2[w] = s2; }
    __syncthreads();
    if (threadIdx.x == 0) {
        float t1 = 0.f, t2 = 0.f;
        #pragma unroll
        for (int i = 0; i < 8; i++) { t1 += sh1[i]; t2 += sh2[i]; }
        float mu = t1 * (1.f / Ev);
        float var = t2 * (1.f / Ev) - mu * mu;
        stats[0] = mu;
        stats[1] = rsqrtf(var + 1e-6f);
    }
    __syncthreads();
    const float mu = stats[0], rstd = stats[1];
    float4 g = *(const float4*)(gamma + threadIdx.x * 4);
    float4 be = *(const float4*)(beta + threadIdx.x * 4);
    float4 o;
    o.x = g.x * (v.x - mu) * rstd + be.x;
    o.y = g.y * (v.y - mu) * rstd + be.y;
    o.z = g.z * (v.z - mu) * rstd + be.z;
    o.w = g.w * (v.w - mu) * rstd + be.w;
    *(float4*)(out + (size_t)r * Ev + threadIdx.x * 4) = o;
}

// ---------------------------------------------------------------------------
extern "C" void kernel_launch(void* const* d_in, const int* in_sizes, int n_in,
                              void* d_out, int out_size) {
    const float* x     = (const float*)d_in[0];
    const float* mask  = (const float*)d_in[1];
    const float* Wq    = (const float*)d_in[2];
    const float* bq    = (const float*)d_in[3];
    const float* Wk    = (const float*)d_in[4];
    const float* bk    = (const float*)d_in[5];
    const float* Wv    = (const float*)d_in[6];
    const float* bv    = (const float*)d_in[7];
    const float* Wo    = (const float*)d_in[8];
    const float* bo    = (const float*)d_in[9];
    const float* gamma = (const float*)d_in[10];
    const float* beta  = (const float*)d_in[11];
    float* out = (float*)d_out;

    __half *Xh, *Qh, *Kh, *Vh, *Ch, *WT;
    float *Ob;
    cudaGetSymbolAddress((void**)&Xh, g_Xh);
    cudaGetSymbolAddress((void**)&Qh, g_Qh);
    cudaGetSymbolAddress((void**)&Kh, g_Kh);
    cudaGetSymbolAddress((void**)&Vh, g_Vh);
    cudaGetSymbolAddress((void**)&Ch, g_Ch);
    cudaGetSymbolAddress((void**)&Ob, g_O);
    cudaGetSymbolAddress((void**)&WT, g_WT);
    __half* WTq = WT;
    __half* WTk = WT + 1ull * Ev * Ev;
    __half* WTv = WT + 2ull * Ev * Ev;
    __half* WTo = WT + 3ull * Ev * Ev;

    cudaFuncSetAttribute(gemm_h<true>,  cudaFuncAttributeMaxDynamicSharedMemorySize, GEMM_SMEM);
    cudaFuncSetAttribute(gemm_h<false>, cudaFuncAttributeMaxDynamicSharedMemorySize, GEMM_SMEM);
    cudaFuncSetAttribute(attn_h, cudaFuncAttributeMaxDynamicSharedMemorySize, ATTN_SMEM);

    cvtX<<<BSz * Ev / 1024, 256>>>(x, Xh);
    cvtW4<<<dim3(32, 32, 4), dim3(32, 8)>>>(Wq, Wk, Wv, Wo, WT);

    dim3 gg(8, 64);
    gemm_h<true><<<gg, 256, GEMM_SMEM>>>(Xh, WTq, bq, Qh, 0.03125f, nullptr);
    gemm_h<true><<<gg, 256, GEMM_SMEM>>>(Xh, WTk, bk, Kh, 1.f, nullptr);
    gemm_h<true><<<gg, 256, GEMM_SMEM>>>(Xh, WTv, bv, Vh, 1.f, nullptr);

    attn_h<<<dim3(Sv / 128, Bv * Hv), 512, ATTN_SMEM>>>(Qh, Kh, Vh, mask, Ch);

    gemm_h<false><<<gg, 256, GEMM_SMEM>>>(Ch, WTo, bo, Ob, 1.f, x);

    ln_kernel<<<BSz, 256>>>(Ob, gamma, beta, out);
}